// round 1
// baseline (speedup 1.0000x reference)
#include <cuda_runtime.h>
#include <math.h>

// -------- static scratch (no allocation allowed) --------
#define MAXN 50176
__device__ float g_neigh[MAXN * 128];   // neighbor mean, [N][128]
__device__ float g_Wgs[128 * 128];      // Wg + Ws

// -------- kernel 1: Wgs = Wg + Ws --------
__global__ void prep_weights(const float* __restrict__ Wg, const float* __restrict__ Ws) {
    int i = blockIdx.x * blockDim.x + threadIdx.x;
    if (i < 128 * 128) g_Wgs[i] = Wg[i] + Ws[i];
}

// -------- kernel 2: neighbor mean aggregation (one warp per node) --------
__global__ void aggregate(const float* __restrict__ x, const int* __restrict__ src,
                          const int* __restrict__ dst, const int* __restrict__ deg,
                          int N, int E) {
    int node = (int)((blockIdx.x * blockDim.x + threadIdx.x) >> 5);
    int lane = threadIdx.x & 31;
    if (node >= N) return;
    int d = deg[node];

    // dst is sorted (repeat(arange(N), deg)); lower_bound gives the edge offset.
    int start = 0;
    if (d > 0) {
        int lo = 0, hi = E;
        while (lo < hi) { int mid = (lo + hi) >> 1; if (dst[mid] < node) lo = mid + 1; else hi = mid; }
        start = lo;
    }

    float4 acc = make_float4(0.f, 0.f, 0.f, 0.f);
    const float4* xv = (const float4*)x;
    for (int jb = 0; jb < d; jb += 32) {
        int rem = d - jb;
        int cnt = rem < 32 ? rem : 32;
        int myidx = (lane < cnt) ? src[start + jb + lane] : 0;
        for (int j = 0; j < cnt; j++) {
            int s = __shfl_sync(0xffffffffu, myidx, j);
            float4 v = xv[(size_t)s * 32 + lane];
            acc.x += v.x; acc.y += v.y; acc.z += v.z; acc.w += v.w;
        }
    }
    float inv = (d > 0) ? (1.0f / (float)d) : 0.0f;
    acc.x *= inv; acc.y *= inv; acc.z *= inv; acc.w *= inv;
    ((float4*)g_neigh)[(size_t)node * 32 + lane] = acc;
}

// -------- kernel 3: fused GEMM  out = elu([x|m] @ [Wgs|Wl]^T + b) --------
// Persistent blocks (grid ~= SM count). Weights fully in smem (131072 B,
// broadcast reads). A-tile (32 nodes x 256 k) staged in smem with XOR chunk
// swizzle for conflict-free column reads.
__global__ void __launch_bounds__(256, 1)
gemm_fused(const float* __restrict__ x, const float* __restrict__ Wl,
           const float* __restrict__ bias, float* __restrict__ out, int N) {
    extern __shared__ float smem[];
    float4* sWv = (float4*)smem;            // 8192 float4: [mat(2)][o(128)][kc(32)]
    float4* sAv = (float4*)(smem + 32768);  // 2048 float4: [n(32)][kc(64)] swizzled

    int tid = threadIdx.x;
    int n   = tid & 31;       // node within tile (lane id)
    int og  = tid >> 5;       // output group (warp id), 8 groups of 16 outputs
    int o0  = og * 16;

    // load weights: linear copy, coalesced gmem + conflict-free STS
    const float4* wgsv = (const float4*)g_Wgs;
    const float4* wlv  = (const float4*)Wl;
    #pragma unroll
    for (int it = 0; it < 32; it++) {
        int idx = it * 256 + tid;           // 0..8191
        sWv[idx] = (idx < 4096) ? wgsv[idx] : wlv[idx - 4096];
    }

    // per-thread bias registers (fixed outputs across all chunks)
    float bv[16];
    #pragma unroll
    for (int i = 0; i < 16; i++) bv[i] = bias[o0 + i];

    int nc = (N + 31) >> 5;   // node chunks of 32
    for (int c = blockIdx.x; c < nc; c += gridDim.x) {
        __syncthreads();      // protects sA reuse (and first-iter sW visibility)
        int base = c * 32;
        // stage A: rows = x[node] (kc 0..31) then g_neigh[node] (kc 32..63)
        #pragma unroll
        for (int it = 0; it < 8; it++) {
            int idx = it * 256 + tid;       // 0..2047
            int an = idx >> 6, kc = idx & 63;
            int node = base + an;
            float4 v = make_float4(0.f, 0.f, 0.f, 0.f);
            if (node < N) {
                v = (kc < 32) ? ((const float4*)x)[(size_t)node * 32 + kc]
                              : ((const float4*)g_neigh)[(size_t)node * 32 + (kc - 32)];
            }
            sAv[an * 64 + (kc ^ (an & 7))] = v;
        }
        __syncthreads();

        float acc[16];
        #pragma unroll
        for (int i = 0; i < 16; i++) acc[i] = 0.f;

        #pragma unroll 4
        for (int kc = 0; kc < 64; kc++) {
            float4 a4 = sAv[n * 64 + (kc ^ (n & 7))];
            const float4* wb = &sWv[(kc >> 5) * 4096 + o0 * 32 + (kc & 31)];
            #pragma unroll
            for (int oi = 0; oi < 16; oi++) {
                float4 b4 = wb[oi * 32];    // broadcast across warp
                acc[oi] = fmaf(a4.x, b4.x, acc[oi]);
                acc[oi] = fmaf(a4.y, b4.y, acc[oi]);
                acc[oi] = fmaf(a4.z, b4.z, acc[oi]);
                acc[oi] = fmaf(a4.w, b4.w, acc[oi]);
            }
        }

        int node = base + n;
        if (node < N) {
            float ov[16];
            #pragma unroll
            for (int oi = 0; oi < 16; oi++) {
                float v = acc[oi] + bv[oi];
                ov[oi] = (v > 0.f) ? v : expm1f(v);
            }
            float4* op = (float4*)(out + (size_t)node * 128 + o0);
            #pragma unroll
            for (int q = 0; q < 4; q++)
                op[q] = make_float4(ov[4*q], ov[4*q+1], ov[4*q+2], ov[4*q+3]);
        }
    }
}

// -------- kernel 4: deg==0 fixup: out = elu(x @ Wg^T + b) (overwrite) --------
__global__ void fixup_deg0(const float* __restrict__ x, const float* __restrict__ Wg,
                           const float* __restrict__ bias, const int* __restrict__ deg,
                           float* __restrict__ out, int N) {
    int node = (int)((blockIdx.x * blockDim.x + threadIdx.x) >> 5);
    int lane = threadIdx.x & 31;
    if (node >= N) return;
    if (deg[node] != 0) return;

    float acc[4] = {0.f, 0.f, 0.f, 0.f};
    const float4* xv = (const float4*)(x + (size_t)node * 128);
    const float4* wv = (const float4*)Wg;
    #pragma unroll 8
    for (int kc = 0; kc < 32; kc++) {
        float4 a = xv[kc];                  // uniform across warp (broadcast)
        #pragma unroll
        for (int j = 0; j < 4; j++) {
            int o = lane + 32 * j;
            float4 w = wv[o * 32 + kc];
            acc[j] = fmaf(a.x, w.x, acc[j]);
            acc[j] = fmaf(a.y, w.y, acc[j]);
            acc[j] = fmaf(a.z, w.z, acc[j]);
            acc[j] = fmaf(a.w, w.w, acc[j]);
        }
    }
    #pragma unroll
    for (int j = 0; j < 4; j++) {
        int o = lane + 32 * j;
        float v = acc[j] + bias[o];
        out[(size_t)node * 128 + o] = (v > 0.f) ? v : expm1f(v);
    }
}

extern "C" void kernel_launch(void* const* d_in, const int* in_sizes, int n_in,
                              void* d_out, int out_size) {
    const float* x  = (const float*)d_in[0];
    const float* Wg = (const float*)d_in[1];
    const float* Wl = (const float*)d_in[2];
    const float* Ws = (const float*)d_in[3];
    const float* b  = (const float*)d_in[4];
    const int* src  = (const int*)d_in[5];
    const int* dst  = (const int*)d_in[6];
    const int* deg  = (const int*)d_in[7];
    int E = in_sizes[5];
    int N = in_sizes[7];
    float* out = (float*)d_out;

    int sm_count = 148;
    cudaDeviceGetAttribute(&sm_count, cudaDevAttrMultiProcessorCount, 0);

    const int smem_bytes = (32768 + 8192) * 4;  // 163840
    cudaFuncSetAttribute(gemm_fused, cudaFuncAttributeMaxDynamicSharedMemorySize, smem_bytes);

    prep_weights<<<64, 256>>>(Wg, Ws);
    aggregate<<<(N + 7) / 8, 256>>>(x, src, dst, deg, N, E);
    gemm_fused<<<sm_count, 256, smem_bytes>>>(x, Wl, b, out, N);
    fixup_deg0<<<(N + 7) / 8, 256>>>(x, Wg, b, deg, out, N);
}

// round 2
// speedup vs baseline: 1.1843x; 1.1843x over previous
#include <cuda_runtime.h>
#include <math.h>

// -------- static scratch (no allocation allowed) --------
#define MAXN 50176
__device__ float g_neigh[MAXN * 128];   // neighbor mean, [N][128]
__device__ float g_Wgs[128 * 128];      // Wg + Ws  ([O][K])
__device__ float g_WgT[128 * 128];      // Wg transposed ([K][O]) for fixup
__device__ int   g_off[MAXN];           // edge start offset per node
__device__ int   g_zlist[MAXN];         // compacted deg==0 node ids
__device__ int   g_zcnt;

// packed fp32x2 FMA (Blackwell FFMA2 — 2 FMA per instruction)
#define FMA2(d, a, b, c) \
    asm("fma.rn.f32x2 %0, %1, %2, %3;" : "=l"(d) : "l"(a), "l"(b), "l"(c))

// -------- kernel 1: Wgs = Wg + Ws, WgT = Wg^T, reset counter --------
__global__ void prep(const float* __restrict__ Wg, const float* __restrict__ Ws) {
    int i = blockIdx.x * blockDim.x + threadIdx.x;
    if (i == 0) g_zcnt = 0;
    if (i < 128 * 128) {
        float wg = Wg[i];
        g_Wgs[i] = wg + Ws[i];
        int o = i >> 7, k = i & 127;
        g_WgT[k * 128 + o] = wg;
    }
}

// -------- kernel 2: per-node edge offsets (binary search) + deg==0 compaction ----
__global__ void offsets(const int* __restrict__ dst, const int* __restrict__ deg,
                        int N, int E) {
    int n = blockIdx.x * blockDim.x + threadIdx.x;
    if (n >= N) return;
    int d = deg[n];
    int lo = 0;
    if (d > 0) {
        int hi = E;
        while (lo < hi) { int mid = (lo + hi) >> 1; if (dst[mid] < n) lo = mid + 1; else hi = mid; }
    } else {
        int p = atomicAdd(&g_zcnt, 1);
        g_zlist[p] = n;
    }
    g_off[n] = lo;
}

// -------- kernel 3: neighbor mean aggregation (one warp per node) --------
__global__ void aggregate(const float* __restrict__ x, const int* __restrict__ src,
                          const int* __restrict__ deg, int N) {
    int node = (int)((blockIdx.x * blockDim.x + threadIdx.x) >> 5);
    int lane = threadIdx.x & 31;
    if (node >= N) return;
    int d = deg[node];
    int start = g_off[node];

    float4 acc = make_float4(0.f, 0.f, 0.f, 0.f);
    const float4* xv = (const float4*)x;
    for (int jb = 0; jb < d; jb += 32) {
        int rem = d - jb;
        int cnt = rem < 32 ? rem : 32;
        int myidx = (lane < cnt) ? __ldg(src + start + jb + lane) : 0;
        for (int j = 0; j < cnt; j++) {
            int s = __shfl_sync(0xffffffffu, myidx, j);
            float4 v = xv[(size_t)s * 32 + lane];
            acc.x += v.x; acc.y += v.y; acc.z += v.z; acc.w += v.w;
        }
    }
    float inv = (d > 0) ? (1.0f / (float)d) : 0.0f;
    acc.x *= inv; acc.y *= inv; acc.z *= inv; acc.w *= inv;
    ((float4*)g_neigh)[(size_t)node * 32 + lane] = acc;
}

// -------- kernel 4: fused GEMM  out = elu([x|m] @ [Wgs|Wl]^T + b) --------
// 64-node tiles, packed f32x2 FMA. Weights (128KB) + A tile (64KB) in smem.
__global__ void __launch_bounds__(256, 1)
gemm_fused(const float* __restrict__ x, const float* __restrict__ Wl,
           const float* __restrict__ bias, float* __restrict__ out, int N) {
    extern __shared__ float smem[];
    float4* sWv = (float4*)smem;            // 8192 float4: [mat(2)][o(128)][kc(32)]
    float4* sAv = (float4*)(smem + 32768);  // 4096 float4: [an(64)][kc(64)] swizzled

    int tid = threadIdx.x;
    int n   = tid & 31;       // lane: node within half-tile
    int og  = tid >> 5;       // warp: output group (16 outputs)
    int o0  = og * 16;

    // load weights: coalesced gmem, conflict-free STS
    const float4* wgsv = (const float4*)g_Wgs;
    const float4* wlv  = (const float4*)Wl;
    #pragma unroll
    for (int it = 0; it < 32; it++) {
        int idx = it * 256 + tid;           // 0..8191
        sWv[idx] = (idx < 4096) ? wgsv[idx] : wlv[idx - 4096];
    }

    float bv[16];
    #pragma unroll
    for (int i = 0; i < 16; i++) bv[i] = bias[o0 + i];

    int nc = (N + 63) >> 6;   // node chunks of 64
    for (int c = blockIdx.x; c < nc; c += gridDim.x) {
        __syncthreads();      // protects sA reuse (and first-iter sW visibility)
        int base = c * 64;
        // stage A: 64 nodes x 256 k; rows = x (kc 0..31) then neigh_mean (kc 32..63)
        #pragma unroll
        for (int it = 0; it < 16; it++) {
            int idx = it * 256 + tid;       // 0..4095
            int an = idx >> 6, kc = idx & 63;
            int node = base + an;
            float4 v = make_float4(0.f, 0.f, 0.f, 0.f);
            if (node < N) {
                v = (kc < 32) ? ((const float4*)x)[(size_t)node * 32 + kc]
                              : ((const float4*)g_neigh)[(size_t)node * 32 + (kc - 32)];
            }
            sAv[an * 64 + (kc ^ (an & 7))] = v;
        }
        __syncthreads();

        unsigned long long acc[2][16];
        #pragma unroll
        for (int r = 0; r < 2; r++)
            #pragma unroll
            for (int i = 0; i < 16; i++) acc[r][i] = 0ull;

        const ulonglong2* sA2 = (const ulonglong2*)sAv;
        const ulonglong2* sW2 = (const ulonglong2*)sWv;

        #pragma unroll 4
        for (int kc = 0; kc < 64; kc++) {
            int sw = kc ^ (n & 7);
            ulonglong2 a0 = sA2[n * 64 + sw];
            ulonglong2 a1 = sA2[(n + 32) * 64 + sw];
            const ulonglong2* wb = &sW2[(kc >> 5) * 4096 + o0 * 32 + (kc & 31)];
            #pragma unroll
            for (int oi = 0; oi < 16; oi++) {
                ulonglong2 b = wb[oi * 32];   // broadcast across warp
                FMA2(acc[0][oi], a0.x, b.x, acc[0][oi]);
                FMA2(acc[0][oi], a0.y, b.y, acc[0][oi]);
                FMA2(acc[1][oi], a1.x, b.x, acc[1][oi]);
                FMA2(acc[1][oi], a1.y, b.y, acc[1][oi]);
            }
        }

        #pragma unroll
        for (int r = 0; r < 2; r++) {
            int node = base + n + 32 * r;
            if (node < N) {
                float ov[16];
                #pragma unroll
                for (int oi = 0; oi < 16; oi++) {
                    float lo, hi;
                    asm("mov.b64 {%0, %1}, %2;" : "=f"(lo), "=f"(hi) : "l"(acc[r][oi]));
                    float v = lo + hi + bv[oi];
                    ov[oi] = (v > 0.f) ? v : expm1f(v);
                }
                float4* op = (float4*)(out + (size_t)node * 128 + o0);
                #pragma unroll
                for (int q = 0; q < 4; q++)
                    op[q] = make_float4(ov[4*q], ov[4*q+1], ov[4*q+2], ov[4*q+3]);
            }
        }
    }
}

// -------- kernel 5: deg==0 fixup over compacted list: out = elu(x @ Wg^T + b) ----
__global__ void fixup_deg0(const float* __restrict__ x, const float* __restrict__ bias,
                           float* __restrict__ out) {
    int cnt = g_zcnt;
    int warp = (int)((blockIdx.x * blockDim.x + threadIdx.x) >> 5);
    int lane = threadIdx.x & 31;
    int nwarps = (gridDim.x * blockDim.x) >> 5;
    const float4* wt = (const float4*)g_WgT;   // [K][O]: row k = 32 float4

    for (int i = warp; i < cnt; i += nwarps) {
        int node = g_zlist[i];
        const float* xr = x + (size_t)node * 128;
        float4 acc = make_float4(0.f, 0.f, 0.f, 0.f);
        #pragma unroll 8
        for (int k = 0; k < 128; k++) {
            float a = __ldg(xr + k);           // uniform broadcast
            float4 w = wt[k * 32 + lane];      // coalesced, L1/L2 hot
            acc.x = fmaf(a, w.x, acc.x);
            acc.y = fmaf(a, w.y, acc.y);
            acc.z = fmaf(a, w.z, acc.z);
            acc.w = fmaf(a, w.w, acc.w);
        }
        float4 bb = ((const float4*)bias)[lane];
        acc.x += bb.x; acc.y += bb.y; acc.z += bb.z; acc.w += bb.w;
        acc.x = (acc.x > 0.f) ? acc.x : expm1f(acc.x);
        acc.y = (acc.y > 0.f) ? acc.y : expm1f(acc.y);
        acc.z = (acc.z > 0.f) ? acc.z : expm1f(acc.z);
        acc.w = (acc.w > 0.f) ? acc.w : expm1f(acc.w);
        ((float4*)(out + (size_t)node * 128))[lane] = acc;
    }
}

extern "C" void kernel_launch(void* const* d_in, const int* in_sizes, int n_in,
                              void* d_out, int out_size) {
    const float* x  = (const float*)d_in[0];
    const float* Wg = (const float*)d_in[1];
    const float* Wl = (const float*)d_in[2];
    const float* Ws = (const float*)d_in[3];
    const float* b  = (const float*)d_in[4];
    const int* src  = (const int*)d_in[5];
    const int* dst  = (const int*)d_in[6];
    const int* deg  = (const int*)d_in[7];
    int E = in_sizes[5];
    int N = in_sizes[7];
    float* out = (float*)d_out;

    int sm_count = 148;
    cudaDeviceGetAttribute(&sm_count, cudaDevAttrMultiProcessorCount, 0);

    const int smem_bytes = (32768 + 16384) * 4;  // 196608
    cudaFuncSetAttribute(gemm_fused, cudaFuncAttributeMaxDynamicSharedMemorySize, smem_bytes);

    prep<<<64, 256>>>(Wg, Ws);
    offsets<<<(N + 255) / 256, 256>>>(dst, deg, N, E);
    aggregate<<<(N + 7) / 8, 256>>>(x, src, deg, N);
    gemm_fused<<<sm_count, 256, smem_bytes>>>(x, Wl, b, out, N);
    fixup_deg0<<<64, 256>>>(x, b, out);
}

// round 4
// speedup vs baseline: 1.6920x; 1.4287x over previous
#include <cuda_runtime.h>
#include <cuda_bf16.h>
#include <math.h>
#include <stdint.h>

// ---------------- static scratch (no allocation allowed) ----------------
#define MAXN 50176
__device__ float    g_neigh[MAXN * 128];   // neighbor mean [N][128]
__device__ float    g_WgT[128 * 128];      // Wg^T ([K][O]) for deg==0 fixup
__device__ uint16_t g_Bhi[128 * 256];      // bf16 hi of B = [Wg+Ws | Wl], [O][256]
__device__ uint16_t g_Blo[128 * 256];      // bf16 lo residual
__device__ int      g_off[MAXN];
__device__ int      g_zlist[MAXN];
__device__ int      g_zcnt;

__device__ __forceinline__ uint32_t smem_u32(const void* p) {
    uint32_t a;
    asm("{ .reg .u64 t; cvta.to.shared.u64 t, %1; cvt.u32.u64 %0, t; }" : "=r"(a) : "l"(p));
    return a;
}

// split fp32 pair -> packed bf16x2 hi + lo words
__device__ __forceinline__ void split2(float a, float b, uint32_t& hw, uint32_t& lw) {
    __nv_bfloat16 ah = __float2bfloat16_rn(a), bh = __float2bfloat16_rn(b);
    float ar = a - __bfloat162float(ah), br = b - __bfloat162float(bh);
    __nv_bfloat16 al = __float2bfloat16_rn(ar), bl = __float2bfloat16_rn(br);
    hw = (uint32_t)__bfloat16_as_ushort(ah) | ((uint32_t)__bfloat16_as_ushort(bh) << 16);
    lw = (uint32_t)__bfloat16_as_ushort(al) | ((uint32_t)__bfloat16_as_ushort(bl) << 16);
}

#define LDSM_X4(r0, r1, r2, r3, addr) \
    asm volatile("ldmatrix.sync.aligned.m8n8.x4.shared.b16 {%0,%1,%2,%3}, [%4];" \
        : "=r"(r0), "=r"(r1), "=r"(r2), "=r"(r3) : "r"(addr))

#define MMA_BF16(d, a, b0, b1) \
    asm volatile("mma.sync.aligned.m16n8k16.row.col.f32.bf16.bf16.f32 " \
        "{%0,%1,%2,%3}, {%4,%5,%6,%7}, {%8,%9}, {%0,%1,%2,%3};" \
        : "+f"((d)[0]), "+f"((d)[1]), "+f"((d)[2]), "+f"((d)[3]) \
        : "r"((a)[0]), "r"((a)[1]), "r"((a)[2]), "r"((a)[3]), "r"(b0), "r"(b1))

// ---------------- kernel 1: build B (hi/lo bf16), WgT, reset counter ----------------
__global__ void prep(const float* __restrict__ Wg, const float* __restrict__ Wl,
                     const float* __restrict__ Ws) {
    int i = blockIdx.x * blockDim.x + threadIdx.x;
    if (i == 0) g_zcnt = 0;
    if (i < 128 * 256) {
        int o = i >> 8, k = i & 255;
        float v = (k < 128) ? (Wg[o * 128 + k] + Ws[o * 128 + k]) : Wl[o * 128 + (k - 128)];
        __nv_bfloat16 h = __float2bfloat16_rn(v);
        __nv_bfloat16 l = __float2bfloat16_rn(v - __bfloat162float(h));
        g_Bhi[i] = __bfloat16_as_ushort(h);
        g_Blo[i] = __bfloat16_as_ushort(l);
    }
    if (i < 128 * 128) {
        int o = i >> 7, k = i & 127;
        g_WgT[k * 128 + o] = Wg[i];
    }
}

// ---------------- kernel 2: per-node edge offsets + deg==0 compaction ----------------
__global__ void offsets(const int* __restrict__ dst, const int* __restrict__ deg,
                        int N, int E) {
    int n = blockIdx.x * blockDim.x + threadIdx.x;
    if (n >= N) return;
    int d = deg[n];
    int lo = 0;
    if (d > 0) {
        int hi = E;
        while (lo < hi) { int mid = (lo + hi) >> 1; if (dst[mid] < n) lo = mid + 1; else hi = mid; }
    } else {
        int p = atomicAdd(&g_zcnt, 1);
        g_zlist[p] = n;
    }
    g_off[n] = lo;
}

// ---------------- kernel 3: neighbor mean aggregation (one warp per node) ----------------
__global__ void aggregate(const float* __restrict__ x, const int* __restrict__ src,
                          const int* __restrict__ deg, int N) {
    int node = (int)((blockIdx.x * blockDim.x + threadIdx.x) >> 5);
    int lane = threadIdx.x & 31;
    if (node >= N) return;
    int d = deg[node];
    int start = g_off[node];

    float4 acc = make_float4(0.f, 0.f, 0.f, 0.f);
    const float4* xv = (const float4*)x;
    for (int jb = 0; jb < d; jb += 32) {
        int rem = d - jb;
        int cnt = rem < 32 ? rem : 32;
        int myidx = (lane < cnt) ? __ldg(src + start + jb + lane) : 0;
        for (int j = 0; j < cnt; j++) {
            int s = __shfl_sync(0xffffffffu, myidx, j);
            float4 v = xv[(size_t)s * 32 + lane];
            acc.x += v.x; acc.y += v.y; acc.z += v.z; acc.w += v.w;
        }
    }
    float inv = (d > 0) ? (1.0f / (float)d) : 0.0f;
    acc.x *= inv; acc.y *= inv; acc.z *= inv; acc.w *= inv;
    ((float4*)g_neigh)[(size_t)node * 32 + lane] = acc;
}

// ---------------- kernel 4: HMMA (mma.sync bf16 hi/lo split) GEMM ----------------
// out = elu([x|neigh] @ B^T + b), B = [Wg+Ws | Wl], 3-pass bf16 split.
// Persistent CTAs, 256 threads (8 warps, 4x2). Tile: 128 nodes x 128 outputs.
// B hi/lo resident in swizzled smem; A staged per 64-K chunk, converted on the fly.
#define SM_BHI   0
#define SM_BLO   65536
#define SM_AHI   131072
#define SM_ALO   147456
#define SM_BIAS  163840
#define SM_TOTAL 164352

__global__ void __launch_bounds__(256, 1)
gemm_mma(const float* __restrict__ x, const float* __restrict__ bias,
         float* __restrict__ out, int N) {
    extern __shared__ char sm[];
    uint32_t sb = smem_u32(sm);
    int tid  = threadIdx.x;
    int wid  = tid >> 5;
    int lane = tid & 31;
    int m_warp = (wid & 3) * 32;
    int n_warp = (wid >> 2) * 64;

    // ---- load B hi/lo into swizzled smem (once per CTA) ----
    {
        const uint4* bh = (const uint4*)g_Bhi;   // 4096 uint4 ([128][32])
        const uint4* bl = (const uint4*)g_Blo;
        #pragma unroll
        for (int it = 0; it < 16; it++) {
            int ci = it * 256 + tid;             // 0..4095
            int n = ci >> 5, c = ci & 31;
            int sw = (c & ~7) | ((c ^ n) & 7);
            *(uint4*)(sm + SM_BHI + n * 512 + sw * 16) = bh[ci];
            *(uint4*)(sm + SM_BLO + n * 512 + sw * 16) = bl[ci];
        }
        if (tid < 128) ((float*)(sm + SM_BIAS))[tid] = bias[tid];
    }

    // ---- precompute ldmatrix lane address components ----
    // A: row = m_warp + mt*16 + (lane&15); k halves by lane>>4
    int a_row0 = m_warp + (lane & 15);           // mt=0 row (mt=1: +16)
    int a_khalf = (lane >> 4) & 1;               // +16 bytes
    // B: n = n_warp + ng*16 + (lane&7) + ((lane>>4)&1)*8 ; k half by (lane>>3)&1
    int b_nl = (lane & 7) + ((lane >> 4) & 1) * 8;
    int b_khalf = (lane >> 3) & 1;

    int ntiles = (N + 127) >> 7;
    const float4* xv = (const float4*)x;
    const float4* mv = (const float4*)g_neigh;

    int arow = tid >> 1;          // staging: this thread's A row (0..127)
    int ahalf = tid & 1;          // k half within 64-chunk (0..31 / 32..63 fp32)

    for (int c = blockIdx.x; c < ntiles; c += gridDim.x) {
        float d[2][8][4];
        #pragma unroll
        for (int mt = 0; mt < 2; mt++)
            #pragma unroll
            for (int nt = 0; nt < 8; nt++)
                #pragma unroll
                for (int q = 0; q < 4; q++) d[mt][nt][q] = 0.f;

        int base = c * 128;

        #pragma unroll
        for (int kb = 0; kb < 4; kb++) {
            // ---- stage A chunk kb: rows=nodes, k in [kb*64, kb*64+64) ----
            __syncthreads();     // previous chunk's ldmatrix reads done
            {
                int node = base + arow;
                bool valid = node < N;
                const float4* srcv = (kb < 2 ? xv : mv)
                    + (size_t)node * 32 + (kb & 1) * 16 + ahalf * 8;
                float4 f[8];
                #pragma unroll
                for (int j = 0; j < 8; j++)
                    f[j] = valid ? srcv[j] : make_float4(0.f, 0.f, 0.f, 0.f);
                #pragma unroll
                for (int j2 = 0; j2 < 4; j2++) {
                    uint4 hi, lo;
                    split2(f[2*j2].x,   f[2*j2].y,   hi.x, lo.x);
                    split2(f[2*j2].z,   f[2*j2].w,   hi.y, lo.y);
                    split2(f[2*j2+1].x, f[2*j2+1].y, hi.z, lo.z);
                    split2(f[2*j2+1].z, f[2*j2+1].w, hi.w, lo.w);
                    int cc = ahalf * 4 + j2;
                    int sw = cc ^ (arow & 7);
                    *(uint4*)(sm + SM_AHI + arow * 128 + sw * 16) = hi;
                    *(uint4*)(sm + SM_ALO + arow * 128 + sw * 16) = lo;
                }
            }
            __syncthreads();

            // ---- compute: 4 k16 steps on this chunk, 3 passes folded ----
            #pragma unroll
            for (int step = 0; step < 4; step++) {
                uint32_t ah[2][4], al[2][4];
                #pragma unroll
                for (int mt = 0; mt < 2; mt++) {
                    int r = a_row0 + mt * 16;
                    int cb = (step * 2 + a_khalf) ^ (r & 7);
                    uint32_t addr = sb + (uint32_t)(r * 128 + cb * 16);
                    LDSM_X4(ah[mt][0], ah[mt][1], ah[mt][2], ah[mt][3], addr + SM_AHI);
                    LDSM_X4(al[mt][0], al[mt][1], al[mt][2], al[mt][3], addr + SM_ALO);
                }
                uint32_t bh[4][4], blr[4][4];
                #pragma unroll
                for (int ng = 0; ng < 4; ng++) {
                    int n = n_warp + ng * 16 + b_nl;
                    int cc = kb * 8 + step * 2 + b_khalf;     // 0..31
                    int sw = (cc & ~7) | ((cc ^ n) & 7);
                    uint32_t addr = sb + (uint32_t)(n * 512 + sw * 16);
                    LDSM_X4(bh[ng][0], bh[ng][1], bh[ng][2], bh[ng][3], addr + SM_BHI);
                    LDSM_X4(blr[ng][0], blr[ng][1], blr[ng][2], blr[ng][3], addr + SM_BLO);
                }
                #pragma unroll
                for (int mt = 0; mt < 2; mt++)
                    #pragma unroll
                    for (int ng = 0; ng < 4; ng++)
                        #pragma unroll
                        for (int sub = 0; sub < 2; sub++) {
                            int nt = ng * 2 + sub;
                            MMA_BF16(d[mt][nt], ah[mt], bh[ng][sub*2], bh[ng][sub*2+1]);
                            MMA_BF16(d[mt][nt], ah[mt], blr[ng][sub*2], blr[ng][sub*2+1]);
                            MMA_BF16(d[mt][nt], al[mt], bh[ng][sub*2], bh[ng][sub*2+1]);
                        }
            }
        }

        // ---- epilogue: bias + ELU + store ----
        const float* sBias = (const float*)(sm + SM_BIAS);
        int g = lane >> 2, t = lane & 3;
        #pragma unroll
        for (int mt = 0; mt < 2; mt++) {
            int row0 = base + m_warp + mt * 16 + g;
            #pragma unroll
            for (int nt = 0; nt < 8; nt++) {
                int col = n_warp + nt * 8 + t * 2;
                float b0 = sBias[col], b1 = sBias[col + 1];
                #pragma unroll
                for (int hrow = 0; hrow < 2; hrow++) {
                    int row = row0 + hrow * 8;
                    if (row < N) {
                        float v0 = d[mt][nt][hrow * 2 + 0] + b0;
                        float v1 = d[mt][nt][hrow * 2 + 1] + b1;
                        v0 = (v0 > 0.f) ? v0 : expm1f(v0);
                        v1 = (v1 > 0.f) ? v1 : expm1f(v1);
                        *(float2*)(out + (size_t)row * 128 + col) = make_float2(v0, v1);
                    }
                }
            }
        }
    }
}

// ---------------- kernel 5: deg==0 fixup: out = elu(x @ Wg^T + b) ----------------
__global__ void fixup_deg0(const float* __restrict__ x, const float* __restrict__ bias,
                           float* __restrict__ out) {
    int cnt = g_zcnt;
    int warp = (int)((blockIdx.x * blockDim.x + threadIdx.x) >> 5);
    int lane = threadIdx.x & 31;
    int nwarps = (gridDim.x * blockDim.x) >> 5;
    const float4* wt = (const float4*)g_WgT;

    for (int i = warp; i < cnt; i += nwarps) {
        int node = g_zlist[i];
        const float* xr = x + (size_t)node * 128;
        float4 acc = make_float4(0.f, 0.f, 0.f, 0.f);
        #pragma unroll 8
        for (int k = 0; k < 128; k++) {
            float a = __ldg(xr + k);
            float4 w = wt[k * 32 + lane];
            acc.x = fmaf(a, w.x, acc.x);
            acc.y = fmaf(a, w.y, acc.y);
            acc.z = fmaf(a, w.z, acc.z);
            acc.w = fmaf(a, w.w, acc.w);
        }
        float4 bb = ((const float4*)bias)[lane];
        acc.x += bb.x; acc.y += bb.y; acc.z += bb.z; acc.w += bb.w;
        acc.x = (acc.x > 0.f) ? acc.x : expm1f(acc.x);
        acc.y = (acc.y > 0.f) ? acc.y : expm1f(acc.y);
        acc.z = (acc.z > 0.f) ? acc.z : expm1f(acc.z);
        acc.w = (acc.w > 0.f) ? acc.w : expm1f(acc.w);
        ((float4*)(out + (size_t)node * 128))[lane] = acc;
    }
}

extern "C" void kernel_launch(void* const* d_in, const int* in_sizes, int n_in,
                              void* d_out, int out_size) {
    const float* x  = (const float*)d_in[0];
    const float* Wg = (const float*)d_in[1];
    const float* Wl = (const float*)d_in[2];
    const float* Ws = (const float*)d_in[3];
    const float* b  = (const float*)d_in[4];
    const int* src  = (const int*)d_in[5];
    const int* dst  = (const int*)d_in[6];
    const int* deg  = (const int*)d_in[7];
    int E = in_sizes[5];
    int N = in_sizes[7];
    float* out = (float*)d_out;

    int sm_count = 148;
    cudaDeviceGetAttribute(&sm_count, cudaDevAttrMultiProcessorCount, 0);

    cudaFuncSetAttribute(gemm_mma, cudaFuncAttributeMaxDynamicSharedMemorySize, SM_TOTAL);

    prep<<<(128 * 256 + 255) / 256, 256>>>(Wg, Wl, Ws);
    offsets<<<(N + 255) / 256, 256>>>(dst, deg, N, E);
    aggregate<<<(N + 7) / 8, 256>>>(x, src, deg, N);
    gemm_mma<<<sm_count, 256, SM_TOTAL>>>(x, b, out, N);
    fixup_deg0<<<64, 256>>>(x, b, out);
}

// round 5
// speedup vs baseline: 1.8731x; 1.1070x over previous
#include <cuda_runtime.h>
#include <cuda_bf16.h>
#include <math.h>
#include <stdint.h>

// ---------------- static scratch (no allocation allowed) ----------------
#define MAXN 50176
__device__ float    g_neigh[MAXN * 128];   // neighbor mean [N][128]
__device__ float    g_WgT[128 * 128];      // Wg^T ([K][O]) for deg==0 fixup
__device__ uint16_t g_Bhi[128 * 256];      // bf16 hi of B = [Wg+Ws | Wl], [O][256]
__device__ uint16_t g_Blo[128 * 256];      // bf16 lo residual
__device__ int      g_off[MAXN];
__device__ int      g_zlist[MAXN];
__device__ int      g_zcnt;

__device__ __forceinline__ uint32_t smem_u32(const void* p) {
    uint32_t a;
    asm("{ .reg .u64 t; cvta.to.shared.u64 t, %1; cvt.u32.u64 %0, t; }" : "=r"(a) : "l"(p));
    return a;
}

// split fp32 pair -> packed bf16x2 hi + lo words
__device__ __forceinline__ void split2(float a, float b, uint32_t& hw, uint32_t& lw) {
    __nv_bfloat16 ah = __float2bfloat16_rn(a), bh = __float2bfloat16_rn(b);
    float ar = a - __bfloat162float(ah), br = b - __bfloat162float(bh);
    __nv_bfloat16 al = __float2bfloat16_rn(ar), bl = __float2bfloat16_rn(br);
    hw = (uint32_t)__bfloat16_as_ushort(ah) | ((uint32_t)__bfloat16_as_ushort(bh) << 16);
    lw = (uint32_t)__bfloat16_as_ushort(al) | ((uint32_t)__bfloat16_as_ushort(bl) << 16);
}

#define LDSM_X4(r0, r1, r2, r3, addr) \
    asm volatile("ldmatrix.sync.aligned.m8n8.x4.shared.b16 {%0,%1,%2,%3}, [%4];" \
        : "=r"(r0), "=r"(r1), "=r"(r2), "=r"(r3) : "r"(addr))

#define MMA_BF16(d, a, b0, b1) \
    asm volatile("mma.sync.aligned.m16n8k16.row.col.f32.bf16.bf16.f32 " \
        "{%0,%1,%2,%3}, {%4,%5,%6,%7}, {%8,%9}, {%0,%1,%2,%3};" \
        : "+f"((d)[0]), "+f"((d)[1]), "+f"((d)[2]), "+f"((d)[3]) \
        : "r"((a)[0]), "r"((a)[1]), "r"((a)[2]), "r"((a)[3]), "r"(b0), "r"(b1))

// ---------------- kernel 1: build B (hi/lo bf16), WgT, reset counter ----------------
__global__ void prep(const float* __restrict__ Wg, const float* __restrict__ Wl,
                     const float* __restrict__ Ws) {
    int i = blockIdx.x * blockDim.x + threadIdx.x;
    if (i == 0) g_zcnt = 0;
    if (i < 128 * 256) {
        int o = i >> 8, k = i & 255;
        float v = (k < 128) ? (Wg[o * 128 + k] + Ws[o * 128 + k]) : Wl[o * 128 + (k - 128)];
        __nv_bfloat16 h = __float2bfloat16_rn(v);
        __nv_bfloat16 l = __float2bfloat16_rn(v - __bfloat162float(h));
        g_Bhi[i] = __bfloat16_as_ushort(h);
        g_Blo[i] = __bfloat16_as_ushort(l);
    }
    if (i < 128 * 128) {
        int o = i >> 7, k = i & 127;
        g_WgT[k * 128 + o] = Wg[i];
    }
}

// ---------------- kernel 2: per-node edge offsets + deg==0 compaction ----------------
__global__ void offsets(const int* __restrict__ dst, const int* __restrict__ deg,
                        int N, int E) {
    int n = blockIdx.x * blockDim.x + threadIdx.x;
    if (n >= N) return;
    int d = deg[n];
    int lo = 0;
    if (d > 0) {
        int hi = E;
        while (lo < hi) { int mid = (lo + hi) >> 1; if (dst[mid] < n) lo = mid + 1; else hi = mid; }
    } else {
        int p = atomicAdd(&g_zcnt, 1);
        g_zlist[p] = n;
    }
    g_off[n] = lo;
}

// ---------------- kernel 3: neighbor mean aggregation (one warp per node) ----------------
__global__ void aggregate(const float* __restrict__ x, const int* __restrict__ src,
                          const int* __restrict__ deg, int N) {
    int node = (int)((blockIdx.x * blockDim.x + threadIdx.x) >> 5);
    int lane = threadIdx.x & 31;
    if (node >= N) return;
    int d = deg[node];
    int start = g_off[node];

    float4 acc = make_float4(0.f, 0.f, 0.f, 0.f);
    const float4* xv = (const float4*)x;
    for (int jb = 0; jb < d; jb += 32) {
        int rem = d - jb;
        int cnt = rem < 32 ? rem : 32;
        int myidx = (lane < cnt) ? __ldg(src + start + jb + lane) : 0;
        #pragma unroll 4
        for (int j = 0; j < cnt; j++) {
            int s = __shfl_sync(0xffffffffu, myidx, j);
            float4 v = xv[(size_t)s * 32 + lane];
            acc.x += v.x; acc.y += v.y; acc.z += v.z; acc.w += v.w;
        }
    }
    float inv = (d > 0) ? (1.0f / (float)d) : 0.0f;
    acc.x *= inv; acc.y *= inv; acc.z *= inv; acc.w *= inv;
    ((float4*)g_neigh)[(size_t)node * 32 + lane] = acc;
}

// ---------------- kernel 4: HMMA GEMM, double-buffered + prefetch, 512 thr ----------------
// out = elu([x|neigh] @ B^T + b), B = [Wg+Ws | Wl], 3-pass bf16 split.
// 16 warps (4m x 4n); tile 128 nodes x 128 outputs; B resident; A double-buffered.
#define SM_BHI   0
#define SM_BLO   65536
#define SM_A     131072          /* 2 bufs x (16KB hi + 16KB lo) */
#define SM_BIAS  196608
#define SM_TOTAL 197120

__device__ __forceinline__ void store_chunk(char* abase, int arow, int aq, const float4* f) {
    #pragma unroll
    for (int j2 = 0; j2 < 2; j2++) {
        uint4 hi, lo;
        split2(f[2*j2].x,   f[2*j2].y,   hi.x, lo.x);
        split2(f[2*j2].z,   f[2*j2].w,   hi.y, lo.y);
        split2(f[2*j2+1].x, f[2*j2+1].y, hi.z, lo.z);
        split2(f[2*j2+1].z, f[2*j2+1].w, hi.w, lo.w);
        int cc = aq * 2 + j2;
        int sw = cc ^ (arow & 7);
        *(uint4*)(abase + arow * 128 + sw * 16) = hi;              // hi
        *(uint4*)(abase + 16384 + arow * 128 + sw * 16) = lo;      // lo
    }
}

__global__ void __launch_bounds__(512, 1)
gemm_mma(const float* __restrict__ x, const float* __restrict__ bias,
         float* __restrict__ out, int N) {
    extern __shared__ char sm[];
    uint32_t sb = smem_u32(sm);
    int tid  = threadIdx.x;
    int wid  = tid >> 5;
    int lane = tid & 31;
    int m_warp = (wid & 3) * 32;
    int n_warp = (wid >> 2) * 32;

    // ---- load B hi/lo into swizzled smem (once per CTA) ----
    {
        const uint4* bh = (const uint4*)g_Bhi;   // 4096 uint4 ([128][32])
        const uint4* bl = (const uint4*)g_Blo;
        #pragma unroll
        for (int it = 0; it < 8; it++) {
            int ci = it * 512 + tid;             // 0..4095
            int n = ci >> 5, c = ci & 31;
            int sw = (c & ~7) | ((c ^ n) & 7);
            *(uint4*)(sm + SM_BHI + n * 512 + sw * 16) = bh[ci];
            *(uint4*)(sm + SM_BLO + n * 512 + sw * 16) = bl[ci];
        }
        if (tid < 128) ((float*)(sm + SM_BIAS))[tid] = bias[tid];
    }

    // ldmatrix lane address components
    int a_row0  = m_warp + (lane & 15);
    int a_khalf = (lane >> 4) & 1;
    int b_nl    = (lane & 7) + ((lane >> 4) & 1) * 8;
    int b_khalf = (lane >> 3) & 1;

    int arow = tid >> 2;          // staging row 0..127
    int aq   = tid & 3;           // k-quarter (16 k values)
    const float4* xv = (const float4*)x;
    const float4* mv = (const float4*)g_neigh;

    int ntiles = (N + 127) >> 7;

    for (int c0 = blockIdx.x; c0 < ntiles; c0 += gridDim.x) {
        int base = c0 * 128;
        int node = base + arow;
        bool valid = node < N;

        float d[2][4][4];
        #pragma unroll
        for (int mt = 0; mt < 2; mt++)
            #pragma unroll
            for (int nt = 0; nt < 4; nt++)
                #pragma unroll
                for (int q = 0; q < 4; q++) d[mt][nt][q] = 0.f;

        // ---- stage chunk 0 into buf 0 ----
        {
            const float4* s = xv + (size_t)node * 32 + aq * 4;
            float4 f[4];
            #pragma unroll
            for (int j = 0; j < 4; j++)
                f[j] = valid ? s[j] : make_float4(0.f, 0.f, 0.f, 0.f);
            store_chunk(sm + SM_A, arow, aq, f);
        }
        __syncthreads();

        #pragma unroll
        for (int kb = 0; kb < 4; kb++) {
            // ---- prefetch chunk kb+1 into registers ----
            float4 nf[4];
            if (kb < 3) {
                const float4* s = ((kb + 1) < 2 ? xv : mv)
                    + (size_t)node * 32 + ((kb + 1) & 1) * 16 + aq * 4;
                #pragma unroll
                for (int j = 0; j < 4; j++)
                    nf[j] = valid ? s[j] : make_float4(0.f, 0.f, 0.f, 0.f);
            }

            // ---- compute chunk kb from buf kb&1 ----
            uint32_t ahb = sb + SM_A + (uint32_t)(kb & 1) * 32768;
            uint32_t alb = ahb + 16384;
            #pragma unroll
            for (int step = 0; step < 4; step++) {
                uint32_t ah[2][4], al[2][4];
                #pragma unroll
                for (int mt = 0; mt < 2; mt++) {
                    int r = a_row0 + mt * 16;
                    int cb = (step * 2 + a_khalf) ^ (r & 7);
                    uint32_t ad = (uint32_t)(r * 128 + cb * 16);
                    LDSM_X4(ah[mt][0], ah[mt][1], ah[mt][2], ah[mt][3], ahb + ad);
                    LDSM_X4(al[mt][0], al[mt][1], al[mt][2], al[mt][3], alb + ad);
                }
                uint32_t bh[2][4], bl[2][4];
                #pragma unroll
                for (int ng = 0; ng < 2; ng++) {
                    int n = n_warp + ng * 16 + b_nl;
                    int cc = kb * 8 + step * 2 + b_khalf;
                    int sw = (cc & ~7) | ((cc ^ n) & 7);
                    uint32_t ad = sb + (uint32_t)(n * 512 + sw * 16);
                    LDSM_X4(bh[ng][0], bh[ng][1], bh[ng][2], bh[ng][3], ad + SM_BHI);
                    LDSM_X4(bl[ng][0], bl[ng][1], bl[ng][2], bl[ng][3], ad + SM_BLO);
                }
                #pragma unroll
                for (int mt = 0; mt < 2; mt++)
                    #pragma unroll
                    for (int ng = 0; ng < 2; ng++)
                        #pragma unroll
                        for (int sub = 0; sub < 2; sub++) {
                            int nt = ng * 2 + sub;
                            MMA_BF16(d[mt][nt], ah[mt], bh[ng][sub*2], bh[ng][sub*2+1]);
                            MMA_BF16(d[mt][nt], ah[mt], bl[ng][sub*2], bl[ng][sub*2+1]);
                            MMA_BF16(d[mt][nt], al[mt], bh[ng][sub*2], bh[ng][sub*2+1]);
                        }
            }

            // ---- store prefetched chunk into the other buffer ----
            if (kb < 3)
                store_chunk(sm + SM_A + ((kb + 1) & 1) * 32768, arow, aq, nf);
            __syncthreads();
        }

        // ---- epilogue: bias + ELU + store ----
        const float* sBias = (const float*)(sm + SM_BIAS);
        int g = lane >> 2, t = lane & 3;
        #pragma unroll
        for (int mt = 0; mt < 2; mt++) {
            int row0 = base + m_warp + mt * 16 + g;
            #pragma unroll
            for (int nt = 0; nt < 4; nt++) {
                int col = n_warp + nt * 8 + t * 2;
                float b0 = sBias[col], b1 = sBias[col + 1];
                #pragma unroll
                for (int hrow = 0; hrow < 2; hrow++) {
                    int row = row0 + hrow * 8;
                    if (row < N) {
                        float v0 = d[mt][nt][hrow * 2 + 0] + b0;
                        float v1 = d[mt][nt][hrow * 2 + 1] + b1;
                        v0 = (v0 > 0.f) ? v0 : expm1f(v0);
                        v1 = (v1 > 0.f) ? v1 : expm1f(v1);
                        *(float2*)(out + (size_t)row * 128 + col) = make_float2(v0, v1);
                    }
                }
            }
        }
    }
}

// ---------------- kernel 5: deg==0 fixup: out = elu(x @ Wg^T + b) ----------------
__global__ void fixup_deg0(const float* __restrict__ x, const float* __restrict__ bias,
                           float* __restrict__ out) {
    int cnt = g_zcnt;
    int warp = (int)((blockIdx.x * blockDim.x + threadIdx.x) >> 5);
    int lane = threadIdx.x & 31;
    int nwarps = (gridDim.x * blockDim.x) >> 5;
    const float4* wt = (const float4*)g_WgT;

    for (int i = warp; i < cnt; i += nwarps) {
        int node = g_zlist[i];
        const float* xr = x + (size_t)node * 128;
        float4 acc = make_float4(0.f, 0.f, 0.f, 0.f);
        #pragma unroll 8
        for (int k = 0; k < 128; k++) {
            float a = __ldg(xr + k);
            float4 w = wt[k * 32 + lane];
            acc.x = fmaf(a, w.x, acc.x);
            acc.y = fmaf(a, w.y, acc.y);
            acc.z = fmaf(a, w.z, acc.z);
            acc.w = fmaf(a, w.w, acc.w);
        }
        float4 bb = ((const float4*)bias)[lane];
        acc.x += bb.x; acc.y += bb.y; acc.z += bb.z; acc.w += bb.w;
        acc.x = (acc.x > 0.f) ? acc.x : expm1f(acc.x);
        acc.y = (acc.y > 0.f) ? acc.y : expm1f(acc.y);
        acc.z = (acc.z > 0.f) ? acc.z : expm1f(acc.z);
        acc.w = (acc.w > 0.f) ? acc.w : expm1f(acc.w);
        ((float4*)(out + (size_t)node * 128))[lane] = acc;
    }
}

extern "C" void kernel_launch(void* const* d_in, const int* in_sizes, int n_in,
                              void* d_out, int out_size) {
    const float* x  = (const float*)d_in[0];
    const float* Wg = (const float*)d_in[1];
    const float* Wl = (const float*)d_in[2];
    const float* Ws = (const float*)d_in[3];
    const float* b  = (const float*)d_in[4];
    const int* src  = (const int*)d_in[5];
    const int* dst  = (const int*)d_in[6];
    const int* deg  = (const int*)d_in[7];
    int E = in_sizes[5];
    int N = in_sizes[7];
    float* out = (float*)d_out;

    int sm_count = 148;
    cudaDeviceGetAttribute(&sm_count, cudaDevAttrMultiProcessorCount, 0);

    cudaFuncSetAttribute(gemm_mma, cudaFuncAttributeMaxDynamicSharedMemorySize, SM_TOTAL);

    prep<<<(128 * 256 + 255) / 256, 256>>>(Wg, Wl, Ws);
    offsets<<<(N + 255) / 256, 256>>>(dst, deg, N, E);
    aggregate<<<(N + 7) / 8, 256>>>(x, src, deg, N);
    gemm_mma<<<sm_count, 512, SM_TOTAL>>>(x, b, out, N);
    fixup_deg0<<<64, 256>>>(x, b, out);
}

// round 6
// speedup vs baseline: 2.2152x; 1.1827x over previous
#include <cuda_runtime.h>
#include <cuda_fp16.h>
#include <math.h>
#include <stdint.h>

// ---------------- static scratch (no allocation allowed) ----------------
#define MAXN 50176
__device__ __align__(16) uint16_t g_xh[MAXN * 128];     // x in fp16
__device__ __align__(16) uint16_t g_neighh[MAXN * 128]; // neighbor mean in fp16
__device__ float    g_WgT[128 * 128];                   // Wg^T for deg==0 fixup
__device__ __align__(16) uint16_t g_Bh[128 * 256];      // fp16 hi of B = [Wg+Ws | Wl]
__device__ __align__(16) uint16_t g_Bl[128 * 256];      // fp16 lo residual of B
__device__ int      g_off[MAXN];
__device__ int      g_zlist[MAXN];
__device__ int      g_zcnt;

__device__ __forceinline__ uint32_t smem_u32(const void* p) {
    uint32_t a;
    asm("{ .reg .u64 t; cvta.to.shared.u64 t, %1; cvt.u32.u64 %0, t; }" : "=r"(a) : "l"(p));
    return a;
}

#define LDSM_X4(r0, r1, r2, r3, addr) \
    asm volatile("ldmatrix.sync.aligned.m8n8.x4.shared.b16 {%0,%1,%2,%3}, [%4];" \
        : "=r"(r0), "=r"(r1), "=r"(r2), "=r"(r3) : "r"(addr))

#define MMA_F16(d, a, b0, b1) \
    asm volatile("mma.sync.aligned.m16n8k16.row.col.f32.f16.f16.f32 " \
        "{%0,%1,%2,%3}, {%4,%5,%6,%7}, {%8,%9}, {%0,%1,%2,%3};" \
        : "+f"((d)[0]), "+f"((d)[1]), "+f"((d)[2]), "+f"((d)[3]) \
        : "r"((a)[0]), "r"((a)[1]), "r"((a)[2]), "r"((a)[3]), "r"(b0), "r"(b1))

#define CP_ASYNC16(dst, src, sz) \
    asm volatile("cp.async.ca.shared.global [%0], [%1], 16, %2;" \
        :: "r"(dst), "l"(src), "r"(sz) : "memory")
#define CP_COMMIT()  asm volatile("cp.async.commit_group;" ::: "memory")
#define CP_WAIT0()   asm volatile("cp.async.wait_group 0;" ::: "memory")

// ---------------- kernel 1: B fp16 split, WgT, x -> fp16, reset counter ----------------
__global__ void prep(const float* __restrict__ x, const float* __restrict__ Wg,
                     const float* __restrict__ Wl, const float* __restrict__ Ws, int N) {
    int i = blockIdx.x * blockDim.x + threadIdx.x;
    if (i == 0) g_zcnt = 0;
    if (i < 128 * 256) {
        int o = i >> 8, k = i & 255;
        float v = (k < 128) ? (Wg[o * 128 + k] + Ws[o * 128 + k]) : Wl[o * 128 + (k - 128)];
        __half h = __float2half_rn(v);
        __half l = __float2half_rn(v - __half2float(h));
        g_Bh[i] = __half_as_ushort(h);
        g_Bl[i] = __half_as_ushort(l);
    }
    if (i < 128 * 128) {
        int o = i >> 7, k = i & 127;
        g_WgT[k * 128 + o] = Wg[i];
    }
    if (i < N * 64) {
        float2 v = ((const float2*)x)[i];
        ((half2*)g_xh)[i] = __floats2half2_rn(v.x, v.y);
    }
}

// ---------------- kernel 2: per-node edge offsets + deg==0 compaction ----------------
__global__ void offsets(const int* __restrict__ dst, const int* __restrict__ deg,
                        int N, int E) {
    int n = blockIdx.x * blockDim.x + threadIdx.x;
    if (n >= N) return;
    int d = deg[n];
    int lo = 0;
    if (d > 0) {
        int hi = E;
        while (lo < hi) { int mid = (lo + hi) >> 1; if (dst[mid] < n) lo = mid + 1; else hi = mid; }
    } else {
        int p = atomicAdd(&g_zcnt, 1);
        g_zlist[p] = n;
    }
    g_off[n] = lo;
}

// ---------------- kernel 3: neighbor mean (fp16 gather, fp32 accumulate) ----------------
__global__ void aggregate(const int* __restrict__ src, const int* __restrict__ deg, int N) {
    int node = (int)((blockIdx.x * blockDim.x + threadIdx.x) >> 5);
    int lane = threadIdx.x & 31;
    if (node >= N) return;
    int d = deg[node];
    int start = g_off[node];

    float4 acc = make_float4(0.f, 0.f, 0.f, 0.f);
    const uint2* xh = (const uint2*)g_xh;      // 32 uint2 (=128 halves) per row
    for (int jb = 0; jb < d; jb += 32) {
        int rem = d - jb;
        int cnt = rem < 32 ? rem : 32;
        int myidx = (lane < cnt) ? __ldg(src + start + jb + lane) : 0;
        int j = 0;
        for (; j + 1 < cnt; j += 2) {
            int s0 = __shfl_sync(0xffffffffu, myidx, j);
            int s1 = __shfl_sync(0xffffffffu, myidx, j + 1);
            uint2 w0 = xh[(size_t)s0 * 32 + lane];
            uint2 w1 = xh[(size_t)s1 * 32 + lane];
            float2 a0 = __half22float2(*(const half2*)&w0.x);
            float2 a1 = __half22float2(*(const half2*)&w0.y);
            float2 b0 = __half22float2(*(const half2*)&w1.x);
            float2 b1 = __half22float2(*(const half2*)&w1.y);
            acc.x += a0.x + b0.x; acc.y += a0.y + b0.y;
            acc.z += a1.x + b1.x; acc.w += a1.y + b1.y;
        }
        if (j < cnt) {
            int s0 = __shfl_sync(0xffffffffu, myidx, j);
            uint2 w0 = xh[(size_t)s0 * 32 + lane];
            float2 a0 = __half22float2(*(const half2*)&w0.x);
            float2 a1 = __half22float2(*(const half2*)&w0.y);
            acc.x += a0.x; acc.y += a0.y; acc.z += a1.x; acc.w += a1.y;
        }
    }
    float inv = (d > 0) ? (1.0f / (float)d) : 0.0f;
    half2 h0 = __floats2half2_rn(acc.x * inv, acc.y * inv);
    half2 h1 = __floats2half2_rn(acc.z * inv, acc.w * inv);
    uint2 ov = make_uint2(*(const uint32_t*)&h0, *(const uint32_t*)&h1);
    ((uint2*)g_neighh)[(size_t)node * 32 + lane] = ov;
}

// ---------------- kernel 4: 2-pass fp16 HMMA GEMM, cp.async pipelined ----------------
// out = elu([x|neigh]h @ (Bh + Bl)^T + b).  A hi-only (error ~1.5e-4 << 1e-3).
// 16 warps (4m x 4n), tile 128 nodes x 128 outputs. B hi/lo resident; A double-buffered.
#define SM_BH    0
#define SM_BL    65536
#define SM_A     131072          /* 2 bufs x 16KB */
#define SM_BIAS  163840
#define SM_TOTAL 164352

__global__ void __launch_bounds__(512, 1)
gemm_mma(const float* __restrict__ bias, float* __restrict__ out, int N) {
    extern __shared__ char sm_[];
    uint32_t sb = smem_u32(sm_);
    int tid  = threadIdx.x;
    int wid  = tid >> 5;
    int lane = tid & 31;
    int m_warp = (wid & 3) * 32;
    int n_warp = (wid >> 2) * 32;

    // ---- load B hi/lo into swizzled smem (once per CTA) ----
    {
        const uint4* bh = (const uint4*)g_Bh;   // 128 rows x 32 16B-units
        const uint4* bl = (const uint4*)g_Bl;
        #pragma unroll
        for (int it = 0; it < 8; it++) {
            int ci = it * 512 + tid;             // 0..4095
            int n = ci >> 5, c = ci & 31;
            int sw = (c & ~7) | ((c ^ n) & 7);
            ((uint4*)(sm_ + SM_BH))[n * 32 + sw] = bh[ci];
            ((uint4*)(sm_ + SM_BL))[n * 32 + sw] = bl[ci];
        }
        if (tid < 128) ((float*)(sm_ + SM_BIAS))[tid] = bias[tid];
    }

    // ldmatrix lane address components
    int a_row0  = m_warp + (lane & 15);
    int a_khalf = (lane >> 4) & 1;
    int b_nl    = (lane & 7) + ((lane >> 4) & 1) * 8;
    int b_khalf = (lane >> 3) & 1;

    int arow = tid >> 2;          // staging row 0..127
    int aq   = tid & 3;           // 32B quarter of the 128B chunk-row
    const char* xb = (const char*)g_xh;
    const char* nb = (const char*)g_neighh;

    int ntiles = (N + 127) >> 7;

    for (int c0 = blockIdx.x; c0 < ntiles; c0 += gridDim.x) {
        int base = c0 * 128;
        int node = base + arow;
        bool valid = node < N;
        uint32_t srcsz = valid ? 16u : 0u;
        size_t rowoff = (size_t)(valid ? node : 0) * 256;   // bytes per row (128 halves)

        // stage chunk 0 -> buf 0
        {
            const char* s = xb + rowoff + aq * 32;
            uint32_t dbase = sb + SM_A + (uint32_t)arow * 128;
            CP_ASYNC16(dbase + (uint32_t)(((aq * 2 + 0) ^ (arow & 7)) * 16), s, srcsz);
            CP_ASYNC16(dbase + (uint32_t)(((aq * 2 + 1) ^ (arow & 7)) * 16), s + 16, srcsz);
            CP_COMMIT();
        }

        float d[2][4][4];
        #pragma unroll
        for (int mt = 0; mt < 2; mt++)
            #pragma unroll
            for (int nt = 0; nt < 4; nt++)
                #pragma unroll
                for (int q = 0; q < 4; q++) d[mt][nt][q] = 0.f;

        #pragma unroll
        for (int kb = 0; kb < 4; kb++) {
            CP_WAIT0();
            __syncthreads();
            if (kb < 3) {
                int nkb = kb + 1;
                const char* s = (nkb < 2 ? xb : nb) + rowoff + (nkb & 1) * 128 + aq * 32;
                uint32_t dbase = sb + SM_A + (uint32_t)(nkb & 1) * 16384 + (uint32_t)arow * 128;
                CP_ASYNC16(dbase + (uint32_t)(((aq * 2 + 0) ^ (arow & 7)) * 16), s, srcsz);
                CP_ASYNC16(dbase + (uint32_t)(((aq * 2 + 1) ^ (arow & 7)) * 16), s + 16, srcsz);
                CP_COMMIT();
            }

            uint32_t abase = sb + SM_A + (uint32_t)(kb & 1) * 16384;
            #pragma unroll
            for (int step = 0; step < 4; step++) {
                uint32_t a_[2][4];
                #pragma unroll
                for (int mt = 0; mt < 2; mt++) {
                    int r = a_row0 + mt * 16;
                    int cb = (step * 2 + a_khalf) ^ (r & 7);
                    LDSM_X4(a_[mt][0], a_[mt][1], a_[mt][2], a_[mt][3],
                            abase + (uint32_t)(r * 128 + cb * 16));
                }
                uint32_t bh_[2][4], bl_[2][4];
                #pragma unroll
                for (int ng = 0; ng < 2; ng++) {
                    int n = n_warp + ng * 16 + b_nl;
                    int cc = kb * 8 + step * 2 + b_khalf;
                    int sw = (cc & ~7) | ((cc ^ n) & 7);
                    uint32_t ad = sb + (uint32_t)(n * 512 + sw * 16);
                    LDSM_X4(bh_[ng][0], bh_[ng][1], bh_[ng][2], bh_[ng][3], ad + SM_BH);
                    LDSM_X4(bl_[ng][0], bl_[ng][1], bl_[ng][2], bl_[ng][3], ad + SM_BL);
                }
                #pragma unroll
                for (int mt = 0; mt < 2; mt++)
                    #pragma unroll
                    for (int ng = 0; ng < 2; ng++)
                        #pragma unroll
                        for (int sub = 0; sub < 2; sub++) {
                            int nt = ng * 2 + sub;
                            MMA_F16(d[mt][nt], a_[mt], bh_[ng][sub*2], bh_[ng][sub*2+1]);
                            MMA_F16(d[mt][nt], a_[mt], bl_[ng][sub*2], bl_[ng][sub*2+1]);
                        }
            }
            __syncthreads();
        }

        // ---- epilogue: bias + ELU + store ----
        const float* sBias = (const float*)(sm_ + SM_BIAS);
        int g = lane >> 2, t = lane & 3;
        #pragma unroll
        for (int mt = 0; mt < 2; mt++) {
            int row0 = base + m_warp + mt * 16 + g;
            #pragma unroll
            for (int nt = 0; nt < 4; nt++) {
                int col = n_warp + nt * 8 + t * 2;
                float b0 = sBias[col], b1 = sBias[col + 1];
                #pragma unroll
                for (int hrow = 0; hrow < 2; hrow++) {
                    int row = row0 + hrow * 8;
                    if (row < N) {
                        float v0 = d[mt][nt][hrow * 2 + 0] + b0;
                        float v1 = d[mt][nt][hrow * 2 + 1] + b1;
                        v0 = (v0 > 0.f) ? v0 : expm1f(v0);
                        v1 = (v1 > 0.f) ? v1 : expm1f(v1);
                        *(float2*)(out + (size_t)row * 128 + col) = make_float2(v0, v1);
                    }
                }
            }
        }
    }
}

// ---------------- kernel 5: deg==0 fixup: out = elu(x @ Wg^T + b) ----------------
__global__ void fixup_deg0(const float* __restrict__ x, const float* __restrict__ bias,
                           float* __restrict__ out) {
    int cnt = g_zcnt;
    int warp = (int)((blockIdx.x * blockDim.x + threadIdx.x) >> 5);
    int lane = threadIdx.x & 31;
    int nwarps = (gridDim.x * blockDim.x) >> 5;
    const float4* wt = (const float4*)g_WgT;

    for (int i = warp; i < cnt; i += nwarps) {
        int node = g_zlist[i];
        const float* xr = x + (size_t)node * 128;
        float4 acc = make_float4(0.f, 0.f, 0.f, 0.f);
        #pragma unroll 8
        for (int k = 0; k < 128; k++) {
            float a = __ldg(xr + k);
            float4 w = wt[k * 32 + lane];
            acc.x = fmaf(a, w.x, acc.x);
            acc.y = fmaf(a, w.y, acc.y);
            acc.z = fmaf(a, w.z, acc.z);
            acc.w = fmaf(a, w.w, acc.w);
        }
        float4 bb = ((const float4*)bias)[lane];
        acc.x += bb.x; acc.y += bb.y; acc.z += bb.z; acc.w += bb.w;
        acc.x = (acc.x > 0.f) ? acc.x : expm1f(acc.x);
        acc.y = (acc.y > 0.f) ? acc.y : expm1f(acc.y);
        acc.z = (acc.z > 0.f) ? acc.z : expm1f(acc.z);
        acc.w = (acc.w > 0.f) ? acc.w : expm1f(acc.w);
        ((float4*)(out + (size_t)node * 128))[lane] = acc;
    }
}

extern "C" void kernel_launch(void* const* d_in, const int* in_sizes, int n_in,
                              void* d_out, int out_size) {
    const float* x  = (const float*)d_in[0];
    const float* Wg = (const float*)d_in[1];
    const float* Wl = (const float*)d_in[2];
    const float* Ws = (const float*)d_in[3];
    const float* b  = (const float*)d_in[4];
    const int* src  = (const int*)d_in[5];
    const int* dst  = (const int*)d_in[6];
    const int* deg  = (const int*)d_in[7];
    int E = in_sizes[5];
    int N = in_sizes[7];
    float* out = (float*)d_out;

    int sm_count = 148;
    cudaDeviceGetAttribute(&sm_count, cudaDevAttrMultiProcessorCount, 0);

    cudaFuncSetAttribute(gemm_mma, cudaFuncAttributeMaxDynamicSharedMemorySize, SM_TOTAL);

    prep<<<(N * 64 + 255) / 256, 256>>>(x, Wg, Wl, Ws, N);
    offsets<<<(N + 255) / 256, 256>>>(dst, deg, N, E);
    aggregate<<<(N + 7) / 8, 256>>>(src, deg, N);
    gemm_mma<<<sm_count, 512, SM_TOTAL>>>(b, out, N);
    fixup_deg0<<<64, 256>>>(x, b, out);
}

// round 7
// speedup vs baseline: 2.4322x; 1.0979x over previous
#include <cuda_runtime.h>
#include <cuda_fp16.h>
#include <math.h>
#include <stdint.h>

// ---------------- static scratch (no allocation allowed) ----------------
#define MAXN 50176
__device__ __align__(16) uint16_t g_xh[MAXN * 128];     // x in fp16
__device__ __align__(16) uint16_t g_neighh[MAXN * 128]; // neighbor mean in fp16
__device__ float    g_WgT[128 * 128];                   // Wg^T for deg==0 fixup
__device__ __align__(16) uint16_t g_Bh[128 * 256];      // fp16 B = [Wg+Ws | Wl]
__device__ int      g_off[MAXN];
__device__ int      g_zlist[MAXN];
__device__ int      g_zcnt;

__device__ __forceinline__ uint32_t smem_u32(const void* p) {
    uint32_t a;
    asm("{ .reg .u64 t; cvta.to.shared.u64 t, %1; cvt.u32.u64 %0, t; }" : "=r"(a) : "l"(p));
    return a;
}

#define LDSM_X4(r0, r1, r2, r3, addr) \
    asm volatile("ldmatrix.sync.aligned.m8n8.x4.shared.b16 {%0,%1,%2,%3}, [%4];" \
        : "=r"(r0), "=r"(r1), "=r"(r2), "=r"(r3) : "r"(addr))

#define MMA_F16(d, a, b0, b1) \
    asm volatile("mma.sync.aligned.m16n8k16.row.col.f32.f16.f16.f32 " \
        "{%0,%1,%2,%3}, {%4,%5,%6,%7}, {%8,%9}, {%0,%1,%2,%3};" \
        : "+f"((d)[0]), "+f"((d)[1]), "+f"((d)[2]), "+f"((d)[3]) \
        : "r"((a)[0]), "r"((a)[1]), "r"((a)[2]), "r"((a)[3]), "r"(b0), "r"(b1))

#define CP_ASYNC16(dst, src, sz) \
    asm volatile("cp.async.ca.shared.global [%0], [%1], 16, %2;" \
        :: "r"(dst), "l"(src), "r"(sz) : "memory")
#define CP_COMMIT()  asm volatile("cp.async.commit_group;" ::: "memory")
#define CP_WAIT0()   asm volatile("cp.async.wait_group 0;" ::: "memory")

// ---------------- kernel 1: B fp16, WgT, x -> fp16, reset counter ----------------
__global__ void prep(const float* __restrict__ x, const float* __restrict__ Wg,
                     const float* __restrict__ Wl, const float* __restrict__ Ws, int N) {
    int i = blockIdx.x * blockDim.x + threadIdx.x;
    if (i == 0) g_zcnt = 0;
    if (i < 128 * 256) {
        int o = i >> 8, k = i & 255;
        float v = (k < 128) ? (Wg[o * 128 + k] + Ws[o * 128 + k]) : Wl[o * 128 + (k - 128)];
        g_Bh[i] = __half_as_ushort(__float2half_rn(v));
    }
    if (i < 128 * 128) {
        int o = i >> 7, k = i & 127;
        g_WgT[k * 128 + o] = Wg[i];
    }
    if (i < N * 64) {
        float2 v = ((const float2*)x)[i];
        ((half2*)g_xh)[i] = __floats2half2_rn(v.x, v.y);
    }
}

// ---------------- kernel 2: per-node edge offsets + deg==0 compaction ----------------
__global__ void offsets(const int* __restrict__ dst, const int* __restrict__ deg,
                        int N, int E) {
    int n = blockIdx.x * blockDim.x + threadIdx.x;
    if (n >= N) return;
    int d = deg[n];
    int lo = 0;
    if (d > 0) {
        int hi = E;
        while (lo < hi) { int mid = (lo + hi) >> 1; if (dst[mid] < n) lo = mid + 1; else hi = mid; }
    } else {
        int p = atomicAdd(&g_zcnt, 1);
        g_zlist[p] = n;
    }
    g_off[n] = lo;
}

// ---------------- kernel 3: neighbor mean (fp16 gather, fp32 acc, MLP=4) ----------------
__global__ void aggregate(const int* __restrict__ src, const int* __restrict__ deg, int N) {
    int node = (int)((blockIdx.x * blockDim.x + threadIdx.x) >> 5);
    int lane = threadIdx.x & 31;
    if (node >= N) return;
    int d = deg[node];
    int start = g_off[node];

    float4 acc = make_float4(0.f, 0.f, 0.f, 0.f);
    const uint2* xh = (const uint2*)g_xh;      // 32 uint2 (=128 halves) per row

    for (int jb = 0; jb < d; jb += 32) {
        int rem = d - jb;
        int cnt = rem < 32 ? rem : 32;
        int myidx = (lane < cnt) ? __ldg(src + start + jb + lane) : 0;
        int j = 0;
        for (; j + 3 < cnt; j += 4) {
            int s0 = __shfl_sync(0xffffffffu, myidx, j);
            int s1 = __shfl_sync(0xffffffffu, myidx, j + 1);
            int s2 = __shfl_sync(0xffffffffu, myidx, j + 2);
            int s3 = __shfl_sync(0xffffffffu, myidx, j + 3);
            uint2 w0 = xh[(size_t)s0 * 32 + lane];
            uint2 w1 = xh[(size_t)s1 * 32 + lane];
            uint2 w2 = xh[(size_t)s2 * 32 + lane];
            uint2 w3 = xh[(size_t)s3 * 32 + lane];
            float2 p;
            p = __half22float2(*(const half2*)&w0.x); acc.x += p.x; acc.y += p.y;
            p = __half22float2(*(const half2*)&w0.y); acc.z += p.x; acc.w += p.y;
            p = __half22float2(*(const half2*)&w1.x); acc.x += p.x; acc.y += p.y;
            p = __half22float2(*(const half2*)&w1.y); acc.z += p.x; acc.w += p.y;
            p = __half22float2(*(const half2*)&w2.x); acc.x += p.x; acc.y += p.y;
            p = __half22float2(*(const half2*)&w2.y); acc.z += p.x; acc.w += p.y;
            p = __half22float2(*(const half2*)&w3.x); acc.x += p.x; acc.y += p.y;
            p = __half22float2(*(const half2*)&w3.y); acc.z += p.x; acc.w += p.y;
        }
        for (; j < cnt; j++) {
            int s0 = __shfl_sync(0xffffffffu, myidx, j);
            uint2 w0 = xh[(size_t)s0 * 32 + lane];
            float2 p;
            p = __half22float2(*(const half2*)&w0.x); acc.x += p.x; acc.y += p.y;
            p = __half22float2(*(const half2*)&w0.y); acc.z += p.x; acc.w += p.y;
        }
    }
    float inv = (d > 0) ? (1.0f / (float)d) : 0.0f;
    half2 h0 = __floats2half2_rn(acc.x * inv, acc.y * inv);
    half2 h1 = __floats2half2_rn(acc.z * inv, acc.w * inv);
    uint2 ov = make_uint2(*(const uint32_t*)&h0, *(const uint32_t*)&h1);
    ((uint2*)g_neighh)[(size_t)node * 32 + lane] = ov;
}

// ---------------- kernel 4: single-pass fp16 HMMA GEMM, cp.async pipelined ----------------
// out = elu([x|neigh]h @ Bh^T + b).  16 warps (4m x 4n), tile 128x128.
#define SM_BH    0
#define SM_A     65536           /* 2 bufs x 16KB */
#define SM_BIAS  98304
#define SM_TOTAL 98816

__global__ void __launch_bounds__(512, 1)
gemm_mma(const float* __restrict__ bias, float* __restrict__ out, int N) {
    extern __shared__ char sm_[];
    uint32_t sb = smem_u32(sm_);
    int tid  = threadIdx.x;
    int wid  = tid >> 5;
    int lane = tid & 31;
    int m_warp = (wid & 3) * 32;
    int n_warp = (wid >> 2) * 32;

    // ---- load B into swizzled smem (once per CTA) ----
    {
        const uint4* bh = (const uint4*)g_Bh;   // 128 rows x 32 16B-units
        #pragma unroll
        for (int it = 0; it < 8; it++) {
            int ci = it * 512 + tid;             // 0..4095
            int n = ci >> 5, c = ci & 31;
            int sw = (c & ~7) | ((c ^ n) & 7);
            ((uint4*)(sm_ + SM_BH))[n * 32 + sw] = bh[ci];
        }
        if (tid < 128) ((float*)(sm_ + SM_BIAS))[tid] = bias[tid];
    }

    // ldmatrix lane address components
    int a_row0  = m_warp + (lane & 15);
    int a_khalf = (lane >> 4) & 1;
    int b_nl    = (lane & 7) + ((lane >> 4) & 1) * 8;
    int b_khalf = (lane >> 3) & 1;

    int arow = tid >> 2;          // staging row 0..127
    int aq   = tid & 3;           // 32B quarter of the 128B chunk-row
    const char* xb = (const char*)g_xh;
    const char* nb = (const char*)g_neighh;

    int ntiles = (N + 127) >> 7;

    for (int c0 = blockIdx.x; c0 < ntiles; c0 += gridDim.x) {
        int base = c0 * 128;
        int node = base + arow;
        bool valid = node < N;
        uint32_t srcsz = valid ? 16u : 0u;
        size_t rowoff = (size_t)(valid ? node : 0) * 256;   // bytes per row

        // stage chunk 0 -> buf 0
        {
            const char* s = xb + rowoff + aq * 32;
            uint32_t dbase = sb + SM_A + (uint32_t)arow * 128;
            CP_ASYNC16(dbase + (uint32_t)(((aq * 2 + 0) ^ (arow & 7)) * 16), s, srcsz);
            CP_ASYNC16(dbase + (uint32_t)(((aq * 2 + 1) ^ (arow & 7)) * 16), s + 16, srcsz);
            CP_COMMIT();
        }

        float d[2][4][4];
        #pragma unroll
        for (int mt = 0; mt < 2; mt++)
            #pragma unroll
            for (int nt = 0; nt < 4; nt++)
                #pragma unroll
                for (int q = 0; q < 4; q++) d[mt][nt][q] = 0.f;

        #pragma unroll
        for (int kb = 0; kb < 4; kb++) {
            CP_WAIT0();
            __syncthreads();
            if (kb < 3) {
                int nkb = kb + 1;
                const char* s = (nkb < 2 ? xb : nb) + rowoff + (nkb & 1) * 128 + aq * 32;
                uint32_t dbase = sb + SM_A + (uint32_t)(nkb & 1) * 16384 + (uint32_t)arow * 128;
                CP_ASYNC16(dbase + (uint32_t)(((aq * 2 + 0) ^ (arow & 7)) * 16), s, srcsz);
                CP_ASYNC16(dbase + (uint32_t)(((aq * 2 + 1) ^ (arow & 7)) * 16), s + 16, srcsz);
                CP_COMMIT();
            }

            uint32_t abase = sb + SM_A + (uint32_t)(kb & 1) * 16384;
            #pragma unroll
            for (int step = 0; step < 4; step++) {
                uint32_t a_[2][4];
                #pragma unroll
                for (int mt = 0; mt < 2; mt++) {
                    int r = a_row0 + mt * 16;
                    int cb = (step * 2 + a_khalf) ^ (r & 7);
                    LDSM_X4(a_[mt][0], a_[mt][1], a_[mt][2], a_[mt][3],
                            abase + (uint32_t)(r * 128 + cb * 16));
                }
                uint32_t bh_[2][4];
                #pragma unroll
                for (int ng = 0; ng < 2; ng++) {
                    int n = n_warp + ng * 16 + b_nl;
                    int cc = kb * 8 + step * 2 + b_khalf;
                    int sw = (cc & ~7) | ((cc ^ n) & 7);
                    LDSM_X4(bh_[ng][0], bh_[ng][1], bh_[ng][2], bh_[ng][3],
                            sb + SM_BH + (uint32_t)(n * 512 + sw * 16));
                }
                #pragma unroll
                for (int mt = 0; mt < 2; mt++)
                    #pragma unroll
                    for (int ng = 0; ng < 2; ng++)
                        #pragma unroll
                        for (int sub = 0; sub < 2; sub++)
                            MMA_F16(d[mt][ng * 2 + sub], a_[mt],
                                    bh_[ng][sub * 2], bh_[ng][sub * 2 + 1]);
            }
            __syncthreads();
        }

        // ---- epilogue: bias + ELU + store ----
        const float* sBias = (const float*)(sm_ + SM_BIAS);
        int g = lane >> 2, t = lane & 3;
        #pragma unroll
        for (int mt = 0; mt < 2; mt++) {
            int row0 = base + m_warp + mt * 16 + g;
            #pragma unroll
            for (int nt = 0; nt < 4; nt++) {
                int col = n_warp + nt * 8 + t * 2;
                float b0 = sBias[col], b1 = sBias[col + 1];
                #pragma unroll
                for (int hrow = 0; hrow < 2; hrow++) {
                    int row = row0 + hrow * 8;
                    if (row < N) {
                        float v0 = d[mt][nt][hrow * 2 + 0] + b0;
                        float v1 = d[mt][nt][hrow * 2 + 1] + b1;
                        v0 = (v0 > 0.f) ? v0 : expm1f(v0);
                        v1 = (v1 > 0.f) ? v1 : expm1f(v1);
                        *(float2*)(out + (size_t)row * 128 + col) = make_float2(v0, v1);
                    }
                }
            }
        }
    }
}

// ---------------- kernel 5: deg==0 fixup: out = elu(x @ Wg^T + b) ----------------
__global__ void fixup_deg0(const float* __restrict__ x, const float* __restrict__ bias,
                           float* __restrict__ out) {
    int cnt = g_zcnt;
    int warp = (int)((blockIdx.x * blockDim.x + threadIdx.x) >> 5);
    int lane = threadIdx.x & 31;
    int nwarps = (gridDim.x * blockDim.x) >> 5;
    const float4* wt = (const float4*)g_WgT;

    for (int i = warp; i < cnt; i += nwarps) {
        int node = g_zlist[i];
        const float* xr = x + (size_t)node * 128;
        float4 acc = make_float4(0.f, 0.f, 0.f, 0.f);
        #pragma unroll 8
        for (int k = 0; k < 128; k++) {
            float a = __ldg(xr + k);
            float4 w = wt[k * 32 + lane];
            acc.x = fmaf(a, w.x, acc.x);
            acc.y = fmaf(a, w.y, acc.y);
            acc.z = fmaf(a, w.z, acc.z);
            acc.w = fmaf(a, w.w, acc.w);
        }
        float4 bb = ((const float4*)bias)[lane];
        acc.x += bb.x; acc.y += bb.y; acc.z += bb.z; acc.w += bb.w;
        acc.x = (acc.x > 0.f) ? acc.x : expm1f(acc.x);
        acc.y = (acc.y > 0.f) ? acc.y : expm1f(acc.y);
        acc.z = (acc.z > 0.f) ? acc.z : expm1f(acc.z);
        acc.w = (acc.w > 0.f) ? acc.w : expm1f(acc.w);
        ((float4*)(out + (size_t)node * 128))[lane] = acc;
    }
}

extern "C" void kernel_launch(void* const* d_in, const int* in_sizes, int n_in,
                              void* d_out, int out_size) {
    const float* x  = (const float*)d_in[0];
    const float* Wg = (const float*)d_in[1];
    const float* Wl = (const float*)d_in[2];
    const float* Ws = (const float*)d_in[3];
    const float* b  = (const float*)d_in[4];
    const int* src  = (const int*)d_in[5];
    const int* dst  = (const int*)d_in[6];
    const int* deg  = (const int*)d_in[7];
    int E = in_sizes[5];
    int N = in_sizes[7];
    float* out = (float*)d_out;

    int sm_count = 148;
    cudaDeviceGetAttribute(&sm_count, cudaDevAttrMultiProcessorCount, 0);

    cudaFuncSetAttribute(gemm_mma, cudaFuncAttributeMaxDynamicSharedMemorySize, SM_TOTAL);

    prep<<<(N * 64 + 255) / 256, 256>>>(x, Wg, Wl, Ws, N);
    offsets<<<(N + 255) / 256, 256>>>(dst, deg, N, E);
    aggregate<<<(N + 7) / 8, 256>>>(src, deg, N);
    gemm_mma<<<sm_count, 512, SM_TOTAL>>>(b, out, N);
    fixup_deg0<<<64, 256>>>(x, b, out);
}